// round 4
// baseline (speedup 1.0000x reference)
#include <cuda_runtime.h>
#include <math.h>
#include <stdint.h>

#define B_    256
#define T_    100
#define IN_   784
#define H_    200
#define R_    4
#define N_    128
#define D_    40
#define NCLS  5
#define G4H   800
#define RD    160
#define MSTRIDE 41

#define BPB   2
#define NBLK  (B_/BPB)
#define THREADS 512

// ---------------- device scratch ----------------
__device__ float g_G[B_*T_*G4H];        // x@Wih.T + bih
__device__ float g_Wg4[H_*H_*4];        // [k=200][i=200][g=4]  gate-interleaved Whh
__device__ float g_Wka2[H_*RD*2];       // [k=200][j=160][key,add]
__device__ float g_WrhT[RD*H_];         // [k=160][j=200]

// FFMA2: packed 2xfp32 fma (sm_103a), exact fp32 semantics
#define FFMA2(d, a, b) asm("fma.rn.f32x2 %0, %1, %2, %0;" : "+l"(d) : "l"(a), "l"(b))

// ---------------- weight repack ----------------
__global__ void prep_weights(const float* __restrict__ Whh,
                             const float* __restrict__ Wkey,
                             const float* __restrict__ Wadd,
                             const float* __restrict__ Wrh) {
    int i = blockIdx.x * 256 + threadIdx.x;
    if (i < 160000) {                       // Wg4[(k*200+ii)*4+g] = Whh[g*200+ii][k]
        int k = i / 800, rem = i % 800, ii = rem >> 2, g = rem & 3;
        g_Wg4[i] = Whh[(g * 200 + ii) * 200 + k];
    } else if (i < 224000) {                // Wka2[(k*160+j)*2+w]
        int z = i - 160000;
        int k = z / 320, rem = z % 320, j = rem >> 1, w = rem & 1;
        g_Wka2[z] = w ? Wadd[j * 200 + k] : Wkey[j * 200 + k];
    } else if (i < 256000) {                // WrhT[k][j] = Wrh[j][k]
        int z = i - 224000; int k = z / 200, j = z % 200;
        g_WrhT[z] = Wrh[j * 160 + k];
    }
}

// ---------------- big input GEMM with FFMA2: G = x @ Wih^T + bih ----------------
#define GBM 128
#define GBN 128
#define GBK 16
#define BSTR 132   // Bs row stride (floats): mult of 4 for LDS.64 alignment, +4 pad

__global__ __launch_bounds__(256) void gemm_gates_x(
    const float* __restrict__ X, const float* __restrict__ Wih,
    const float* __restrict__ bih) {
    __shared__ float2 As2[GBK][GBM + 2];   // duplicated (a,a) pairs
    __shared__ float  Bs[GBK][BSTR];
    const int tid = threadIdx.x;
    const int m0 = blockIdx.y * GBM;
    const int n0 = blockIdx.x * GBN;
    const int tx = tid & 15, ty = tid >> 4;

    unsigned long long acc[8][4];
#pragma unroll
    for (int i = 0; i < 8; i++)
#pragma unroll
        for (int j = 0; j < 4; j++) acc[i][j] = 0ull;

    const int ar = tid >> 1, ac = (tid & 1) * 8;
    const int bn = n0 + ar;

    for (int kt = 0; kt < IN_; kt += GBK) {
        {
            const float* src = X + (size_t)(m0 + ar) * IN_ + kt + ac;
            float4 v0 = *(const float4*)src;
            float4 v1 = *(const float4*)(src + 4);
            As2[ac + 0][ar] = make_float2(v0.x, v0.x);
            As2[ac + 1][ar] = make_float2(v0.y, v0.y);
            As2[ac + 2][ar] = make_float2(v0.z, v0.z);
            As2[ac + 3][ar] = make_float2(v0.w, v0.w);
            As2[ac + 4][ar] = make_float2(v1.x, v1.x);
            As2[ac + 5][ar] = make_float2(v1.y, v1.y);
            As2[ac + 6][ar] = make_float2(v1.z, v1.z);
            As2[ac + 7][ar] = make_float2(v1.w, v1.w);
        }
        {
            float4 v0 = make_float4(0.f,0.f,0.f,0.f), v1 = v0;
            if (bn < G4H) {
                const float* src = Wih + (size_t)bn * IN_ + kt + ac;
                v0 = *(const float4*)src;
                v1 = *(const float4*)(src + 4);
            }
            Bs[ac + 0][ar] = v0.x; Bs[ac + 1][ar] = v0.y;
            Bs[ac + 2][ar] = v0.z; Bs[ac + 3][ar] = v0.w;
            Bs[ac + 4][ar] = v1.x; Bs[ac + 5][ar] = v1.y;
            Bs[ac + 6][ar] = v1.z; Bs[ac + 7][ar] = v1.w;
        }
        __syncthreads();
#pragma unroll
        for (int k = 0; k < GBK; k++) {
            unsigned long long ra[8], rb[4];
#pragma unroll
            for (int i = 0; i < 8; i++)
                ra[i] = *(const unsigned long long*)&As2[k][ty + 16 * i];
#pragma unroll
            for (int j = 0; j < 4; j++)
                rb[j] = *(const unsigned long long*)&Bs[k][32 * j + 2 * tx];
#pragma unroll
            for (int i = 0; i < 8; i++)
#pragma unroll
                for (int j = 0; j < 4; j++) FFMA2(acc[i][j], ra[i], rb[j]);
        }
        __syncthreads();
    }
#pragma unroll
    for (int i = 0; i < 8; i++) {
        size_t base = (size_t)(m0 + ty + 16 * i) * G4H;
#pragma unroll
        for (int j = 0; j < 4; j++) {
            int col = n0 + 32 * j + 2 * tx;
            if (col < G4H) {
                union { unsigned long long u; float2 f; } cvt;
                cvt.u = acc[i][j];
                cvt.f.x += bih[col];
                cvt.f.y += bih[col + 1];
                *(float2*)&g_G[base + col] = cvt.f;
            }
        }
    }
}

// ---------------- recurrent kernel ----------------
struct __align__(16) BS {
    float M[N_ * MSTRIDE];   // 5248
    float h[H_];             // 200 (post-LSTM h_t)
    float hpre[H_];          // 200 (h after +r@Wrh)
    float c[H_];             // 200
    float r[RD];             // 160
    float key[RD];           // 160
    float add[RD];           // 160
    float wr[R_ * N_];       // 512
    float wu[N_];            // 128
    float wwsum[N_];         // 128
    float Ksm[R_ * N_];      // 512
    float m2[N_];            // 128
    float wlu[N_];           // 128
    float outh[NCLS];        // 5  (h@Who + bho + bro)
    float key2[R_];          // 4
    float sig;               // 1
    float pad_[2];           // -> 7876 floats = 31504 B (mult of 16)
};
#define BSF (sizeof(BS)/4)

__device__ __forceinline__ float sigmoidf_(float x) { return 1.f / (1.f + expf(-x)); }

__global__ __launch_bounds__(THREADS) void mann_recurrent(
    const float* __restrict__ bkey, const float* __restrict__ badd,
    const float* __restrict__ Wsig, const float* __restrict__ bsig,
    const float* __restrict__ Who,  const float* __restrict__ bho,
    const float* __restrict__ Wro,  const float* __restrict__ bro,
    const float* __restrict__ brh,  const float* __restrict__ bhh,
    float* __restrict__ out) {
    extern __shared__ float smemf[];
    BS* S = reinterpret_cast<BS*>(smemf);
    float* sWrh = smemf + 2 * BSF;   // 32000 floats: WrhT pinned in SMEM

    const int tid = threadIdx.x;
    const int blk = blockIdx.x;
    const int wid = tid >> 5, lane = tid & 31;

    for (int b = 0; b < BPB; b++) {
        BS& s = S[b];
        for (int i = tid; i < N_ * MSTRIDE; i += THREADS) s.M[i] = 0.f;
        for (int i = tid; i < H_; i += THREADS) { s.h[i] = 0.f; s.c[i] = 0.f; }
        for (int i = tid; i < RD; i += THREADS) s.r[i] = 0.f;
        for (int i = tid; i < R_ * N_; i += THREADS) s.wr[i] = 0.f;
        for (int i = tid; i < N_; i += THREADS) s.wu[i] = 0.f;
    }
    for (int i = tid; i < RD * H_; i += THREADS) sWrh[i] = g_WrhT[i];
    __syncthreads();

    const int p_b = (tid < 400) ? tid / 200 : 0;
    const int p_i = (tid < 400) ? tid % 200 : 0;

    for (int t = 0; t < T_; t++) {
        // ---- prefetch this step's G row into registers ----
        float gin0 = 0.f, gin1 = 0.f, gin2 = 0.f, gin3 = 0.f;
        if (tid < 400) {
            const float* Gp = g_G + ((size_t)(blk * BPB + p_b) * T_ + t) * G4H + p_i;
            gin0 = Gp[0]; gin1 = Gp[200]; gin2 = Gp[400]; gin3 = Gp[600];
        }

        // ---- phase 1: hpre = h + r@WrhT + brh | LRU select | prev-step output ----
        if (tid < 400) {
            const float* rr = S[p_b].r;
            float acc = 0.f;
#pragma unroll 8
            for (int k = 0; k < RD; k++) acc += rr[k] * sWrh[k * 200 + p_i];
            S[p_b].hpre[p_i] = S[p_b].h[p_i] + acc + brh[p_i];
        } else if (wid == 13 || wid == 14) {
            // stable 4-smallest of wu (one warp per b)
            int b = wid - 13;
            unsigned long long kv[4];
            float wl[4];
#pragma unroll
            for (int q = 0; q < 4; q++) {
                int n = lane + 32 * q;
                unsigned u = __float_as_uint(S[b].wu[n]);
                u = (u & 0x80000000u) ? ~u : (u | 0x80000000u);
                kv[q] = ((unsigned long long)u << 32) | (unsigned)n;
                wl[q] = 0.f;
            }
#pragma unroll
            for (int ss = 0; ss < 4; ss++) {
                unsigned long long m = kv[0]; int qi = 0;
#pragma unroll
                for (int q = 1; q < 4; q++) if (kv[q] < m) { m = kv[q]; qi = q; }
                unsigned long long wm = m;
#pragma unroll
                for (int o = 16; o > 0; o >>= 1) {
                    unsigned long long x = __shfl_xor_sync(0xffffffffu, wm, o);
                    if (x < wm) wm = x;
                }
                if (m == wm) { wl[qi] = 1.f; kv[qi] = ~0ull; }
            }
#pragma unroll
            for (int q = 0; q < 4; q++) S[b].wlu[lane + 32 * q] = wl[q];
        } else if (wid == 15 && t > 0) {
            // output for step t-1: outh + r@Wro
            for (int p = 0; p < BPB * NCLS; p++) {
                int b = p / NCLS, cls = p % NCLS;
                const float* rr = S[b].r;
                float acc = 0.f;
#pragma unroll
                for (int k = lane; k < RD; k += 32) acc += rr[k] * Wro[cls * RD + k];
#pragma unroll
                for (int o = 16; o > 0; o >>= 1) acc += __shfl_down_sync(0xffffffffu, acc, o);
                if (lane == 0)
                    out[((size_t)(blk * BPB + b) * T_ + (t - 1)) * NCLS + cls] = acc + S[b].outh[cls];
            }
        }
        __syncthreads();

        // ---- phase 2: gates GEMV (gate-interleaved) + LSTM pointwise, fused ----
        if (tid < 400) {
            float a0 = 0.f, a1 = 0.f, a2 = 0.f, a3 = 0.f;
            const float4* W = reinterpret_cast<const float4*>(g_Wg4) + p_i;
            const float* hp = S[p_b].hpre;
#pragma unroll 10
            for (int k = 0; k < H_; k++) {
                float4 w = W[k * 200];
                float hk = hp[k];
                a0 += w.x * hk; a1 += w.y * hk; a2 += w.z * hk; a3 += w.w * hk;
            }
            a0 += gin0 + bhh[p_i];
            a1 += gin1 + bhh[200 + p_i];
            a2 += gin2 + bhh[400 + p_i];
            a3 += gin3 + bhh[600 + p_i];
            float ig = sigmoidf_(a0), fg = sigmoidf_(a1);
            float gg = tanhf(a2),    og = sigmoidf_(a3);
            float ct = fg * S[p_b].c[p_i] + ig * gg;
            S[p_b].c[p_i] = ct;
            S[p_b].h[p_i] = og * tanhf(ct);
        }
        __syncthreads();

        // ---- phase 4: key/add GEMV (pair-interleaved) | sigma | outh ----
        if (tid < 320) {
            int b = tid / 160, j = tid % 160;
            float kk = 0.f, aa = 0.f;
            const float2* W = reinterpret_cast<const float2*>(g_Wka2) + j;
            const float* hh = S[b].h;
#pragma unroll 10
            for (int k = 0; k < H_; k++) {
                float2 w = W[k * 160];
                float hk = hh[k];
                kk += w.x * hk; aa += w.y * hk;
            }
            S[b].key[j] = kk + bkey[j];
            S[b].add[j] = aa + badd[j];
        } else if (wid == 10 || wid == 11) {
            int b = wid - 10;
            float p = 0.f;
            for (int k = lane; k < H_; k += 32) p += S[b].h[k] * Wsig[k];
#pragma unroll
            for (int o = 16; o > 0; o >>= 1) p += __shfl_xor_sync(0xffffffffu, p, o);
            if (lane == 0) S[b].sig = p + bsig[0];
        } else if (wid == 12 || wid == 13) {
            int b = wid - 12;
            const float* hh = S[b].h;
            for (int cls = 0; cls < NCLS; cls++) {
                float acc = 0.f;
#pragma unroll
                for (int k = lane; k < H_; k += 32) acc += hh[k] * Who[cls * H_ + k];
#pragma unroll
                for (int o = 16; o > 0; o >>= 1) acc += __shfl_down_sync(0xffffffffu, acc, o);
                if (lane == 0) S[b].outh[cls] = acc + bho[cls] + bro[cls];
            }
        }
        __syncthreads();

        // ---- phase 6: M update + wwsum + m2 ; key2 ----
        {
            int b = tid >> 8;
            int n = (tid >> 1) & 127;
            int dh = tid & 1;
            BS& s = S[b];
            float sg = s.sig, omsg = 1.f - sg;
            float wl = s.wlu[n];
            float w0 = sg * s.wr[n]       + omsg * wl;
            float w1 = sg * s.wr[128 + n] + omsg * wl;
            float w2 = sg * s.wr[256 + n] + omsg * wl;
            float w3 = sg * s.wr[384 + n] + omsg * wl;
            if (dh == 0) s.wwsum[n] = w0 + w1 + w2 + w3;
            float m2p = 0.f;
            int d0 = dh * 20;
#pragma unroll
            for (int dd = 0; dd < 20; dd++) {
                int d = d0 + dd;
                float mv = s.M[n * MSTRIDE + d] * wl
                         + w0 * s.add[d] + w1 * s.add[40 + d]
                         + w2 * s.add[80 + d] + w3 * s.add[120 + d];
                s.M[n * MSTRIDE + d] = mv;
                m2p += mv * mv;
            }
            m2p += __shfl_xor_sync(0xffffffffu, m2p, 1);
            if (dh == 0) s.m2[n] = m2p;
        }
        if (tid < 8) {
            int b = tid >> 2, r = tid & 3;
            float sum = 0.f;
#pragma unroll
            for (int d = 0; d < D_; d++) { float v = S[b].key[r * 40 + d]; sum += v * v; }
            S[b].key2[r] = sum;
        }
        __syncthreads();

        // ---- phase 7: cosine similarity ----
        for (int e = tid; e < 1024; e += THREADS) {
            int b = e >> 9, rn = e & 511, r = rn >> 7, n = rn & 127;
            BS& s = S[b];
            const float* kp = s.key + r * 40;
            const float* mp = s.M + n * MSTRIDE;
            float dot = 0.f;
#pragma unroll
            for (int d = 0; d < D_; d++) dot += kp[d] * mp[d];
            s.Ksm[rn] = dot / sqrtf(s.key2[r] * s.m2[n] + 1e-6f);
        }
        __syncthreads();

        // ---- phase 8: softmax over n (warp per (b,r)) ----
        if (wid < 8) {
            int b = wid >> 2, r = wid & 3;
            BS& s = S[b];
            float v0 = s.Ksm[r * N_ + lane];
            float v1 = s.Ksm[r * N_ + 32 + lane];
            float v2 = s.Ksm[r * N_ + 64 + lane];
            float v3 = s.Ksm[r * N_ + 96 + lane];
            float mx = fmaxf(fmaxf(v0, v1), fmaxf(v2, v3));
#pragma unroll
            for (int o = 16; o > 0; o >>= 1) mx = fmaxf(mx, __shfl_xor_sync(0xffffffffu, mx, o));
            float e0 = expf(v0 - mx), e1 = expf(v1 - mx), e2 = expf(v2 - mx), e3 = expf(v3 - mx);
            float su = e0 + e1 + e2 + e3;
#pragma unroll
            for (int o = 16; o > 0; o >>= 1) su += __shfl_xor_sync(0xffffffffu, su, o);
            float inv = 1.f / su;
            s.wr[r * N_ + lane]      = e0 * inv;
            s.wr[r * N_ + 32 + lane] = e1 * inv;
            s.wr[r * N_ + 64 + lane] = e2 * inv;
            s.wr[r * N_ + 96 + lane] = e3 * inv;
        }
        __syncthreads();

        // ---- phase 9+10: wu update ; r_t = wr @ M ----
        if (tid < 256) {
            int b = tid >> 7, n = tid & 127;
            BS& s = S[b];
            s.wu[n] = 0.95f * s.wu[n]
                    + (s.wr[n] + s.wr[128 + n] + s.wr[256 + n] + s.wr[384 + n])
                    + s.wwsum[n];
        }
        if (tid < 320) {
            int b = tid / 160, rd = tid % 160;
            int r = rd / 40, d = rd % 40;
            BS& s = S[b];
            const float* wrp = s.wr + r * N_;
            float dot = 0.f;
#pragma unroll 8
            for (int n = 0; n < N_; n++) dot += wrp[n] * s.M[n * MSTRIDE + d];
            s.r[rd] = dot;
        }
        __syncthreads();
    }

    // ---- final output (t = 99) ----
    if (wid == 15) {
        for (int p = 0; p < BPB * NCLS; p++) {
            int b = p / NCLS, cls = p % NCLS;
            const float* rr = S[b].r;
            float acc = 0.f;
#pragma unroll
            for (int k = lane; k < RD; k += 32) acc += rr[k] * Wro[cls * RD + k];
#pragma unroll
            for (int o = 16; o > 0; o >>= 1) acc += __shfl_down_sync(0xffffffffu, acc, o);
            if (lane == 0)
                out[((size_t)(blk * BPB + b) * T_ + (T_ - 1)) * NCLS + cls] = acc + S[b].outh[cls];
        }
    }
}

// ---------------- launch ----------------
extern "C" void kernel_launch(void* const* d_in, const int* in_sizes, int n_in,
                              void* d_out, int out_size) {
    const float* x    = (const float*)d_in[0];
    const float* Wkey = (const float*)d_in[1];
    const float* bkey = (const float*)d_in[2];
    const float* Wadd = (const float*)d_in[3];
    const float* badd = (const float*)d_in[4];
    const float* Wsig = (const float*)d_in[5];
    const float* bsig = (const float*)d_in[6];
    const float* Who  = (const float*)d_in[7];
    const float* bho  = (const float*)d_in[8];
    const float* Wro  = (const float*)d_in[9];
    const float* bro  = (const float*)d_in[10];
    const float* Wrh  = (const float*)d_in[11];
    const float* brh  = (const float*)d_in[12];
    const float* Wih  = (const float*)d_in[13];
    const float* bih  = (const float*)d_in[14];
    const float* Whh  = (const float*)d_in[15];
    const float* bhh  = (const float*)d_in[16];
    float* out = (float*)d_out;

    prep_weights<<<1000, 256>>>(Whh, Wkey, Wadd, Wrh);
    gemm_gates_x<<<dim3((G4H + GBN - 1) / GBN, B_ * T_ / GBM), 256>>>(x, Wih, bih);

    size_t shmem = 2 * sizeof(BS) + (size_t)RD * H_ * 4;
    cudaFuncSetAttribute(mann_recurrent, cudaFuncAttributeMaxDynamicSharedMemorySize, (int)shmem);
    mann_recurrent<<<NBLK, THREADS, shmem>>>(bkey, badd, Wsig, bsig, Who, bho,
                                             Wro, bro, brh, bhh, out);
}